// round 17
// baseline (speedup 1.0000x reference)
#include <cuda_runtime.h>
#include <cuda_bf16.h>
#include <mma.h>
#include <cstdint>

using namespace nvcuda;

#define D 256
#define MAXN 20000
#define MAXE 320000
#define MAXB 64

typedef unsigned long long ull;

// ---------------- scratch (static device allocations; no cudaMalloc) ----------
// Activations are stored UNNORMALIZED in ping-pong buffers g_h / g_htmp;
// per-row reciprocal norms live in g_rnA / g_rnB. Consumers scale at load.
__device__ __align__(16) float g_h[(MAXN + MAXB) * D];     // buffer A
__device__ __align__(16) float g_htmp[(MAXN + MAXB) * D];  // buffer B
__device__ __align__(16) float g_hnv[(MAXN + MAXB) * D];
__device__ float g_rnA[MAXN + MAXB];
__device__ float g_rnB[MAXN + MAXB];
__device__ float g_ssqpart[(MAXN + MAXB) * 2];
__device__ __align__(16) float g_Wc[2 * D * D];   // fused [512,256] fp32 weight
// Row-major bf16 split images of Wc: [512][256]
__device__ __align__(16) __nv_bfloat16 g_Wh[2 * D * D];
__device__ __align__(16) __nv_bfloat16 g_Wl[2 * D * D];
__device__ int   g_deg[MAXN];
__device__ int   g_rowstart[MAXN + 1];
__device__ int   g_cursor[MAXN];
__device__ int   g_csrc[MAXE];
__device__ __align__(16) float g_cw[MAXE];
__device__ int   g_bcnt[MAXB];
__device__ int   g_brow[MAXB + 1];
__device__ int   g_bcur[MAXB];
__device__ int   g_bnodes[MAXN];

// ---------------- block reduction helper ----------------
__device__ __forceinline__ float block_sum_bcast(float v) {
    __shared__ float red[33];
    int lane = threadIdx.x & 31, w = threadIdx.x >> 5;
#pragma unroll
    for (int o = 16; o; o >>= 1) v += __shfl_down_sync(0xffffffffu, v, o);
    __syncthreads();
    if (lane == 0) red[w] = v;
    __syncthreads();
    if (threadIdx.x == 0) {
        float s = 0.f;
        int nw = (blockDim.x + 31) >> 5;
        for (int i = 0; i < nw; i++) s += red[i];
        red[32] = s;
    }
    __syncthreads();
    return red[32];
}

// ---------------- weight fusion: Wc = [W2@linW_top ; W3@linW_bot] -------------
__global__ void k_fuse(const float* __restrict__ W2, const float* __restrict__ W3,
                       const float* __restrict__ linW) {
    int k0 = blockIdx.x * 8;
    int j = threadIdx.x;
    __shared__ float sW[8][D];
    const float* wsrc;
    const float* lsrc;
    if (k0 < D) { wsrc = W2 + (size_t)k0 * D;        lsrc = linW; }
    else        { wsrc = W3 + (size_t)(k0 - D) * D;  lsrc = linW + (size_t)D * D; }
#pragma unroll
    for (int r = 0; r < 8; r++) sW[r][j] = wsrc[r * D + j];
    __syncthreads();
    float acc[8];
#pragma unroll
    for (int r = 0; r < 8; r++) acc[r] = 0.f;
    for (int t = 0; t < D; t++) {
        float lv = lsrc[(size_t)t * D + j];
#pragma unroll
        for (int r = 0; r < 8; r++) acc[r] += sW[r][t] * lv;
    }
#pragma unroll
    for (int r = 0; r < 8; r++) g_Wc[(size_t)(k0 + r) * D + j] = acc[r];
}

// ---------------- weight split: Wc -> row-major bf16 hi/lo --------------------
__global__ void k_wsplit() {
    int i = blockIdx.x * blockDim.x + threadIdx.x;   // 512 x 256 = 131072
    float val = g_Wc[i];
    __nv_bfloat16 hi = __float2bfloat16(val);
    __nv_bfloat16 lo = __float2bfloat16(val - __bfloat162float(hi));
    g_Wh[i] = hi;
    g_Wl[i] = lo;
}

// ---------------- encoding: h = relu(X @ W1) (unnormalized) + rn --------------
__global__ void k_encode(const float* __restrict__ X, const float* __restrict__ Xs,
                         const float* __restrict__ W1, float* __restrict__ h,
                         float* __restrict__ rn, int N) {
    int i = blockIdx.x;
    int d = threadIdx.x;
    const float* xr = (i < N) ? (X + (size_t)i * 2) : (Xs + (size_t)(i - N) * 2);
    float v = fmaxf(xr[0] * W1[d] + xr[1] * W1[D + d], 0.f);
    float ss = block_sum_bcast(v * v);
    h[(size_t)i * D + d] = v;
    if (d == 0) rn[i] = 1.f / fmaxf(sqrtf(ss), 1e-12f);
}

// ---------------- CSR build ----------------
__global__ void k_zero(int N, int B) {
    int i = blockIdx.x * blockDim.x + threadIdx.x;
    if (i < N) { g_deg[i] = 0; g_cursor[i] = 0; }
    if (i < B) { g_bcnt[i] = 0; g_bcur[i] = 0; }
}

__global__ void k_hist(const int* __restrict__ dst, const int* __restrict__ batch,
                       int E, int N) {
    int i = blockIdx.x * blockDim.x + threadIdx.x;
    if (i < E) atomicAdd(&g_deg[dst[i]], 1);
    if (i < N) atomicAdd(&g_bcnt[batch[i]], 1);
}

__global__ void k_scan2(int N, int B) {
    const int* cnt; int* out; int n;
    if (blockIdx.x == 0) { cnt = g_deg;  out = g_rowstart; n = N; }
    else                 { cnt = g_bcnt; out = g_brow;     n = B; }
    __shared__ int s[1024];
    const int T = 1024;
    int t = threadIdx.x;
    int chunk = (n + T - 1) / T;
    int base = t * chunk;
    int run = 0;
    for (int c = 0; c < chunk; c++) { int i = base + c; if (i < n) run += cnt[i]; }
    s[t] = run;
    __syncthreads();
    for (int off = 1; off < T; off <<= 1) {
        int v = (t >= off) ? s[t - off] : 0;
        __syncthreads();
        s[t] += v;
        __syncthreads();
    }
    run = (t > 0) ? s[t - 1] : 0;
    for (int c = 0; c < chunk; c++) {
        int i = base + c;
        if (i < n) { out[i] = run; run += cnt[i]; }
    }
    if (t == T - 1) out[n] = s[T - 1];
}

__global__ void k_scatter(const int* __restrict__ src, const int* __restrict__ dst,
                          const float* __restrict__ w, const int* __restrict__ batch,
                          int E, int N) {
    int i = blockIdx.x * blockDim.x + threadIdx.x;
    if (i < E) {
        int dd = dst[i];
        int pos = g_rowstart[dd] + atomicAdd(&g_cursor[dd], 1);
        g_csrc[pos] = src[i];
        g_cw[pos] = w[i];
    }
    if (i < N) {
        int b = batch[i];
        int pos = g_brow[b] + atomicAdd(&g_bcur[b], 1);
        g_bnodes[pos] = i;
    }
}

// ---------------- merged aggregation (vectorized, 64 threads/block) -----------
// hnv[dst] = sum w * (h[src] * rn[src])  — rn folded into the edge weight.
__global__ void k_gather4(const float* __restrict__ h, const float* __restrict__ rn,
                          float* __restrict__ hnv, int N) {
    int blk = blockIdx.x;
    int c4 = threadIdx.x << 2;
    float4 acc = make_float4(0.f, 0.f, 0.f, 0.f);
    if (blk < N) {
        int s = g_rowstart[blk], e = g_rowstart[blk + 1];
        int j = s;
        for (; j + 2 <= e; j += 2) {
            int   s0 = g_csrc[j],     s1 = g_csrc[j + 1];
            float w0 = g_cw[j] * rn[s0];
            float w1 = g_cw[j + 1] * rn[s1];
            float4 v0 = *reinterpret_cast<const float4*>(&h[(size_t)s0 * D + c4]);
            float4 v1 = *reinterpret_cast<const float4*>(&h[(size_t)s1 * D + c4]);
            acc.x += w0 * v0.x + w1 * v1.x;
            acc.y += w0 * v0.y + w1 * v1.y;
            acc.z += w0 * v0.z + w1 * v1.z;
            acc.w += w0 * v0.w + w1 * v1.w;
        }
        if (j < e) {
            int   s0 = g_csrc[j];
            float w0 = g_cw[j] * rn[s0];
            float4 v0 = *reinterpret_cast<const float4*>(&h[(size_t)s0 * D + c4]);
            acc.x += w0 * v0.x; acc.y += w0 * v0.y;
            acc.z += w0 * v0.z; acc.w += w0 * v0.w;
        }
    } else {
        int b = blk - N;
        int s = g_brow[b], e = g_brow[b + 1];
        int j = s;
        for (; j + 2 <= e; j += 2) {
            int s0 = g_bnodes[j], s1 = g_bnodes[j + 1];
            float r0 = rn[s0], r1 = rn[s1];
            float4 v0 = *reinterpret_cast<const float4*>(&h[(size_t)s0 * D + c4]);
            float4 v1 = *reinterpret_cast<const float4*>(&h[(size_t)s1 * D + c4]);
            acc.x += r0 * v0.x + r1 * v1.x;
            acc.y += r0 * v0.y + r1 * v1.y;
            acc.z += r0 * v0.z + r1 * v1.z;
            acc.w += r0 * v0.w + r1 * v1.w;
        }
        if (j < e) {
            int s0 = g_bnodes[j];
            float r0 = rn[s0];
            float4 v0 = *reinterpret_cast<const float4*>(&h[(size_t)s0 * D + c4]);
            acc.x += r0 * v0.x; acc.y += r0 * v0.y;
            acc.z += r0 * v0.z; acc.w += r0 * v0.w;
        }
    }
    *reinterpret_cast<float4*>(&hnv[(size_t)blk * D + c4]) = acc;
}

// ---------------- wmma GEMM: out = relu([in0*rn | in1] @ Wc + bias) -----------
// R14 PROVEN SHAPE (frozen): BM=64, BN=128, BK=32; 8 warps (2x4), 32x32 tiles,
// static smem, NO pipeline (R15/R16 variants both regressed).
// Adds: in0 rows scaled by rn at A-load; epilogue emits per-row ssq partials.
static const int A_LD = 40;     // bf16 elems per A smem row (32 + pad)
static const int B_LD = 136;    // bf16 elems per B smem row (128 + pad)
static const int S_LD = 132;    // float elems per staging row (128 + pad)

__global__ void k_gemm_wmma(
    const float* __restrict__ in0, const float* __restrict__ rn,
    const float* __restrict__ in1,
    const float* __restrict__ bias, float* __restrict__ outp,
    float* __restrict__ ssqpart, int M) {
    __shared__ __align__(16) char sm[64 * S_LD * 4];
    __nv_bfloat16* Ahi = reinterpret_cast<__nv_bfloat16*>(sm);
    __nv_bfloat16* Alo = Ahi + 64 * A_LD;
    __nv_bfloat16* Bhi = reinterpret_cast<__nv_bfloat16*>(sm + 2 * 64 * A_LD * 2);
    __nv_bfloat16* Blo = Bhi + 32 * B_LD;
    float* stage = reinterpret_cast<float*>(sm);

    int tid = threadIdx.x;
    int wid = tid >> 5;
    int warpRow = wid >> 2;        // 0..1
    int warpCol = wid & 3;         // 0..3
    int row0 = blockIdx.y * 64;
    int col0 = blockIdx.x * 128;

    // per-thread A-row reciprocal norms (rows tid>>3 and tid>>3+32)
    int ar_ = tid >> 3;
    float rs[2];
    rs[0] = (row0 + ar_ < M) ? rn[row0 + ar_] : 0.f;
    rs[1] = (row0 + ar_ + 32 < M) ? rn[row0 + ar_ + 32] : 0.f;

    wmma::fragment<wmma::accumulator, 16, 16, 16, float> acc[2][2];
#pragma unroll
    for (int i = 0; i < 2; i++)
#pragma unroll
        for (int j = 0; j < 2; j++) wmma::fill_fragment(acc[i][j], 0.f);

    for (int t = 0; t < 16; t++) {
        // ---- A tile: 64 rows x 32 k fp32 -> (scaled) hi/lo bf16 in smem ----
        const float* src = (t < 8) ? in0 : in1;
        int kbase = (t & 7) * 32;
#pragma unroll
        for (int it = 0; it < 2; it++) {
            int id = tid + it * 256;       // 0..511
            int r = id >> 3;               // 0..63
            int c4 = (id & 7) << 2;        // 0..28
            int grow = row0 + r;
            float4 v = make_float4(0.f, 0.f, 0.f, 0.f);
            if (grow < M)
                v = *reinterpret_cast<const float4*>(&src[(size_t)grow * D + kbase + c4]);
            if (t < 8) {
                float sc = rs[it];
                v.x *= sc; v.y *= sc; v.z *= sc; v.w *= sc;
            }
            __nv_bfloat16 h0 = __float2bfloat16(v.x), h1 = __float2bfloat16(v.y);
            __nv_bfloat16 h2 = __float2bfloat16(v.z), h3 = __float2bfloat16(v.w);
            __nv_bfloat16 l0 = __float2bfloat16(v.x - __bfloat162float(h0));
            __nv_bfloat16 l1 = __float2bfloat16(v.y - __bfloat162float(h1));
            __nv_bfloat16 l2 = __float2bfloat16(v.z - __bfloat162float(h2));
            __nv_bfloat16 l3 = __float2bfloat16(v.w - __bfloat162float(h3));
            uint2 uh, ul;
            uh.x = (unsigned)__bfloat16_as_ushort(h0) | ((unsigned)__bfloat16_as_ushort(h1) << 16);
            uh.y = (unsigned)__bfloat16_as_ushort(h2) | ((unsigned)__bfloat16_as_ushort(h3) << 16);
            ul.x = (unsigned)__bfloat16_as_ushort(l0) | ((unsigned)__bfloat16_as_ushort(l1) << 16);
            ul.y = (unsigned)__bfloat16_as_ushort(l2) | ((unsigned)__bfloat16_as_ushort(l3) << 16);
            *reinterpret_cast<uint2*>(&Ahi[r * A_LD + c4]) = uh;
            *reinterpret_cast<uint2*>(&Alo[r * A_LD + c4]) = ul;
        }
        // ---- B tile: 32 k x 128 cols bf16 from pre-split images ----
#pragma unroll
        for (int it = 0; it < 2; it++) {
            int id = tid + it * 256;       // 0..511
            int r = id >> 4;               // 0..31
            int c8 = (id & 15) << 3;       // 0..120
            size_t goff = (size_t)(t * 32 + r) * D + col0 + c8;
            *reinterpret_cast<uint4*>(&Bhi[r * B_LD + c8]) =
                *reinterpret_cast<const uint4*>(&g_Wh[goff]);
            *reinterpret_cast<uint4*>(&Blo[r * B_LD + c8]) =
                *reinterpret_cast<const uint4*>(&g_Wl[goff]);
        }
        __syncthreads();

        // ---- compute: 2 k16 sub-steps ----
#pragma unroll
        for (int kk = 0; kk < 32; kk += 16) {
            wmma::fragment<wmma::matrix_a, 16, 16, 16, __nv_bfloat16, wmma::row_major> ah[2], al[2];
            wmma::fragment<wmma::matrix_b, 16, 16, 16, __nv_bfloat16, wmma::row_major> bh[2], bl[2];
#pragma unroll
            for (int i = 0; i < 2; i++) {
                int ar = warpRow * 32 + i * 16;
                wmma::load_matrix_sync(ah[i], &Ahi[ar * A_LD + kk], A_LD);
                wmma::load_matrix_sync(al[i], &Alo[ar * A_LD + kk], A_LD);
            }
#pragma unroll
            for (int j = 0; j < 2; j++) {
                int bc = warpCol * 32 + j * 16;
                wmma::load_matrix_sync(bh[j], &Bhi[kk * B_LD + bc], B_LD);
                wmma::load_matrix_sync(bl[j], &Blo[kk * B_LD + bc], B_LD);
            }
#pragma unroll
            for (int i = 0; i < 2; i++)
#pragma unroll
                for (int j = 0; j < 2; j++) {
                    wmma::mma_sync(acc[i][j], ah[i], bh[j], acc[i][j]);
                    wmma::mma_sync(acc[i][j], ah[i], bl[j], acc[i][j]);
                    wmma::mma_sync(acc[i][j], al[i], bh[j], acc[i][j]);
                }
        }
        __syncthreads();
    }

    // ---- epilogue: stage accum, bias+relu STG, per-row ssq partial ----
#pragma unroll
    for (int i = 0; i < 2; i++)
#pragma unroll
        for (int j = 0; j < 2; j++)
            wmma::store_matrix_sync(
                &stage[(warpRow * 32 + i * 16) * S_LD + warpCol * 32 + j * 16],
                acc[i][j], S_LD, wmma::mem_row_major);
    __syncthreads();
#pragma unroll
    for (int it = 0; it < 8; it++) {
        int id = tid + it * 256;           // 0..2047
        int r = id >> 5;                   // 0..63 (one warp per row)
        int c4 = (id & 31) << 2;           // 0..124
        int gr = row0 + r;
        float4 o = make_float4(0.f, 0.f, 0.f, 0.f);
        if (gr < M) {
            o.x = fmaxf(stage[r * S_LD + c4 + 0] + bias[col0 + c4 + 0], 0.f);
            o.y = fmaxf(stage[r * S_LD + c4 + 1] + bias[col0 + c4 + 1], 0.f);
            o.z = fmaxf(stage[r * S_LD + c4 + 2] + bias[col0 + c4 + 2], 0.f);
            o.w = fmaxf(stage[r * S_LD + c4 + 3] + bias[col0 + c4 + 3], 0.f);
            *reinterpret_cast<float4*>(&outp[(size_t)gr * D + col0 + c4]) = o;
        }
        float ssq = o.x * o.x + o.y * o.y + o.z * o.z + o.w * o.w;
#pragma unroll
        for (int off = 16; off; off >>= 1)
            ssq += __shfl_xor_sync(0xffffffffu, ssq, off);
        if ((tid & 31) == 0 && gr < M)
            ssqpart[gr * 2 + blockIdx.x] = ssq;
    }
}

// ---------------- rn from ssq partials ----------------
__global__ void k_rn(float* __restrict__ rn, int M) {
    int i = blockIdx.x * blockDim.x + threadIdx.x;
    if (i < M) {
        float ss = g_ssqpart[2 * i] + g_ssqpart[2 * i + 1];
        rn[i] = 1.f / fmaxf(sqrtf(ss), 1e-12f);
    }
}

// ---------------- decode (scales by rn at load) ----------------
__global__ void k_decode(const float* __restrict__ h, const float* __restrict__ rn,
                         const int* __restrict__ action_idx,
                         const float* __restrict__ W4, const float* __restrict__ W5,
                         float* __restrict__ out, int N) {
    int b = blockIdx.x;
    int d = threadIdx.x;
    float hsv = h[(size_t)(N + b) * D + d] * rn[N + b];
    float s = block_sum_bcast(hsv * W4[d]);
    int a = action_idx[b];
    float q = fmaxf(h[(size_t)a * D + d] * rn[a] * s, 0.f) * W5[d];
    float Q = block_sum_bcast(q);
    if (d == 0) out[b] = Q;
}

// ---------------- launcher ----------------
extern "C" void kernel_launch(void* const* d_in, const int* in_sizes, int n_in,
                              void* d_out, int out_size) {
    const int*   edge_src     = (const int*)d_in[0];
    const int*   edge_dst     = (const int*)d_in[1];
    const float* edge_w       = (const float*)d_in[2];
    const int*   batch_assign = (const int*)d_in[3];
    const int*   action_idx   = (const int*)d_in[4];
    const float* X            = (const float*)d_in[5];
    const float* Xs           = (const float*)d_in[6];
    const float* W1           = (const float*)d_in[7];
    const float* W2           = (const float*)d_in[8];
    const float* W3           = (const float*)d_in[9];
    const float* linW         = (const float*)d_in[10];
    const float* linb         = (const float*)d_in[11];
    const float* W4           = (const float*)d_in[12];
    const float* W5           = (const float*)d_in[13];
    float* out = (float*)d_out;

    int E = in_sizes[0];
    int N = in_sizes[3];
    int B = in_sizes[4];
    int M = N + B;

    float *p_bufA, *p_bufB, *p_hnv, *p_rnA, *p_rnB, *p_ssq;
    cudaGetSymbolAddress((void**)&p_bufA, g_h);
    cudaGetSymbolAddress((void**)&p_bufB, g_htmp);
    cudaGetSymbolAddress((void**)&p_hnv, g_hnv);
    cudaGetSymbolAddress((void**)&p_rnA, g_rnA);
    cudaGetSymbolAddress((void**)&p_rnB, g_rnB);
    cudaGetSymbolAddress((void**)&p_ssq, g_ssqpart);

    // fused weights + bf16 split + encoding (unnormalized + rn)
    k_fuse<<<64, 256>>>(W2, W3, linW);
    k_wsplit<<<512, 256>>>();
    k_encode<<<M, 256>>>(X, Xs, W1, p_bufA, p_rnA, N);

    // CSR build (edges by dst, nodes by batch)
    k_zero<<<(N + 255) / 256, 256>>>(N, B);
    k_hist<<<(E + 255) / 256, 256>>>(edge_dst, batch_assign, E, N);
    k_scan2<<<2, 1024>>>(N, B);
    k_scatter<<<(E + 255) / 256, 256>>>(edge_src, edge_dst, edge_w, batch_assign, E, N);

    // 3 depths: gather -> wmma GEMM (+ssq partials) -> rn  (ping-pong buffers)
    dim3 ggrid(2, (M + 63) / 64);
    float* bin = p_bufA;  float* rin = p_rnA;
    float* bout = p_bufB; float* rout = p_rnB;
    for (int it = 0; it < 3; it++) {
        k_gather4<<<M, 64>>>(bin, rin, p_hnv, N);
        k_gemm_wmma<<<ggrid, 256>>>(bin, rin, p_hnv, linb, bout, p_ssq, M);
        k_rn<<<(M + 255) / 256, 256>>>(rout, M);
        float* tb = bin; bin = bout; bout = tb;
        float* tr = rin; rin = rout; rout = tr;
    }

    // decode (bin/rin now hold the final depth's output)
    k_decode<<<B, 256>>>(bin, rin, action_idx, W4, W5, out, N);
}